// round 3
// baseline (speedup 1.0000x reference)
#include <cuda_runtime.h>

// Shifted-window attention (UniMatch / Swin style), B=8, H=96, W=128, C=128, NS=4.
// Inputs (metadata order): q[8,12288,128] f32, k, v, attn_mask[16,768,768] f32 (unused:
// recomputed inline from region ids), num_splits, with_shift, h, w (scalars, constant
// for this problem => hardcoded).

namespace {
constexpr int H_IMG = 96, W_IMG = 128, C_DIM = 128;
constexpr int WSH = 24, WSW = 32;          // window size
constexpr int SHF = 12, SWF = 16;          // shift
constexpr int NTOK = WSH * WSW;            // 768 tokens per window
constexpr int BM = 64, BN = 64;
constexpr int NKT = NTOK / BN;             // 12 K tiles
constexpr int NQT = NTOK / BM;             // 12 Q tiles
constexpr int QS_STR = 132;                // Q row-major [BM][132]
constexpr int KT_STR = 65;                 // K transposed [C][65]
constexpr int VS_STR = 132;                // V row-major [BN][132]
constexpr int PS_STR = 68;                 // P row-major [BM][68]
constexpr int KV_FLOATS = (C_DIM * KT_STR > BN * VS_STR) ? C_DIM * KT_STR : BN * VS_STR;
constexpr int SMEM_FLOATS = BM * QS_STR + KV_FLOATS + BM * PS_STR;
constexpr int SMEM_BYTES = SMEM_FLOATS * 4;   // 84992 B -> 2 CTAs/SM
constexpr float INV_SCALE = 0.088388347648318447f;  // 1/sqrt(128)
}

// token index within window -> global token row (applies roll(-12,-16) + window split;
// same map is the inverse merge + roll(+12,+16) for the output)
__device__ __forceinline__ int grow_idx(int b, int wy, int wx, int t) {
    int r = t >> 5, cc = t & 31;
    int hi = wy * WSH + r + SHF; if (hi >= H_IMG) hi -= H_IMG;
    int wi = wx * WSW + cc + SWF; if (wi >= W_IMG) wi -= W_IMG;
    return b * (H_IMG * W_IMG) + hi * W_IMG + wi;
}

// Swin shift-mask region id on the (unrolled) label image
__device__ __forceinline__ int region_of(int wy, int wx, int t) {
    int r = t >> 5, cc = t & 31;
    int hh = wy * WSH + r;
    int ww = wx * WSW + cc;
    int rh = (hh < H_IMG - WSH) ? 0 : ((hh < H_IMG - SHF) ? 1 : 2);
    int rw = (ww < W_IMG - WSW) ? 0 : ((ww < W_IMG - SWF) ? 1 : 2);
    return rh * 3 + rw;
}

__global__ __launch_bounds__(256, 2)
void swin_attn_kernel(const float* __restrict__ q, const float* __restrict__ k,
                      const float* __restrict__ v, float* __restrict__ out) {
    extern __shared__ float smem[];
    float* Qs = smem;                    // [BM][QS_STR]
    float* KV = Qs + BM * QS_STR;        // union: Kt [C][KT_STR] then Vs [BN][VS_STR]
    float* Ps = KV + KV_FLOATS;          // [BM][PS_STR]

    const int tid  = threadIdx.x;
    const int ty   = tid >> 4;           // 0..15
    const int tx   = tid & 15;           // 0..15
    const int lane = tid & 31;
    const int warp = tid >> 5;

    const int win  = blockIdx.y;         // 0..127
    const int b    = win >> 4;
    const int widx = win & 15;
    const int wy   = widx >> 2;
    const int wx   = widx & 3;
    const int qbase = blockIdx.x * BM;

    // ---- load Q tile [64 tokens][128 c], row-major, coalesced ----
    #pragma unroll
    for (int s = 0; s < 8; ++s) {
        int local = warp * 8 + s;
        int row = grow_idx(b, wy, wx, qbase + local);
        float4 val = reinterpret_cast<const float4*>(q + (size_t)row * C_DIM)[lane];
        *reinterpret_cast<float4*>(&Qs[local * QS_STR + lane * 4]) = val;
    }

    int qreg[4];
    float mrun[4], lsum[4];
    float o[4][8];
    #pragma unroll
    for (int i = 0; i < 4; ++i) {
        qreg[i] = region_of(wy, wx, qbase + 4 * ty + i);
        mrun[i] = -1e30f;
        lsum[i] = 0.f;
        #pragma unroll
        for (int u = 0; u < 8; ++u) o[i][u] = 0.f;
    }

    for (int kt = 0; kt < NKT; ++kt) {
        const int kbase = kt * BN;
        __syncthreads();   // prior PV reads of KV/Ps done (also covers Q store at kt=0)

        // ---- load K tile, transposed into Kt[c][t] ----
        #pragma unroll
        for (int s = 0; s < 8; ++s) {
            int local = warp * 8 + s;
            int row = grow_idx(b, wy, wx, kbase + local);
            float4 val = reinterpret_cast<const float4*>(k + (size_t)row * C_DIM)[lane];
            KV[(4 * lane + 0) * KT_STR + local] = val.x;
            KV[(4 * lane + 1) * KT_STR + local] = val.y;
            KV[(4 * lane + 2) * KT_STR + local] = val.z;
            KV[(4 * lane + 3) * KT_STR + local] = val.w;
        }
        __syncthreads();

        // ---- S = Q K^T (4x4 per thread) ----
        float acc[4][4];
        #pragma unroll
        for (int i = 0; i < 4; ++i)
            #pragma unroll
            for (int j = 0; j < 4; ++j) acc[i][j] = 0.f;

        #pragma unroll 4
        for (int c = 0; c < C_DIM; ++c) {
            float qv[4], kv[4];
            #pragma unroll
            for (int i = 0; i < 4; ++i) qv[i] = Qs[(4 * ty + i) * QS_STR + c];  // broadcast
            #pragma unroll
            for (int j = 0; j < 4; ++j) kv[j] = KV[c * KT_STR + 4 * tx + j];
            #pragma unroll
            for (int i = 0; i < 4; ++i)
                #pragma unroll
                for (int j = 0; j < 4; ++j) acc[i][j] = fmaf(qv[i], kv[j], acc[i][j]);
        }
        __syncthreads();   // Kt reads done; KV buffer may now be overwritten by V

        // ---- scale + shift mask + online softmax ----
        int kreg[4];
        #pragma unroll
        for (int j = 0; j < 4; ++j) kreg[j] = region_of(wy, wx, kbase + 4 * tx + j);

        float alpha[4];
        #pragma unroll
        for (int i = 0; i < 4; ++i) {
            float mt = -1e30f;
            #pragma unroll
            for (int j = 0; j < 4; ++j) {
                float s = acc[i][j] * INV_SCALE + ((qreg[i] == kreg[j]) ? 0.f : -100.f);
                acc[i][j] = s;
                mt = fmaxf(mt, s);
            }
            #pragma unroll
            for (int off = 8; off >= 1; off >>= 1)
                mt = fmaxf(mt, __shfl_xor_sync(0xffffffffu, mt, off));
            float mnew = fmaxf(mrun[i], mt);
            alpha[i] = __expf(mrun[i] - mnew);
            float rs = 0.f;
            #pragma unroll
            for (int j = 0; j < 4; ++j) {
                acc[i][j] = __expf(acc[i][j] - mnew);
                rs += acc[i][j];
            }
            #pragma unroll
            for (int off = 8; off >= 1; off >>= 1)
                rs += __shfl_xor_sync(0xffffffffu, rs, off);
            lsum[i] = lsum[i] * alpha[i] + rs;
            mrun[i] = mnew;
        }

        // ---- store P, rescale O, load V tile into KV union ----
        #pragma unroll
        for (int i = 0; i < 4; ++i) {
            *reinterpret_cast<float4*>(&Ps[(4 * ty + i) * PS_STR + 4 * tx]) =
                make_float4(acc[i][0], acc[i][1], acc[i][2], acc[i][3]);
            #pragma unroll
            for (int u = 0; u < 8; ++u) o[i][u] *= alpha[i];
        }
        #pragma unroll
        for (int s = 0; s < 8; ++s) {
            int local = warp * 8 + s;
            int row = grow_idx(b, wy, wx, kbase + local);
            float4 val = reinterpret_cast<const float4*>(v + (size_t)row * C_DIM)[lane];
            *reinterpret_cast<float4*>(&KV[local * VS_STR + lane * 4]) = val;
        }
        __syncthreads();

        // ---- O += P V (4 rows x 8 cols per thread) ----
        #pragma unroll 2
        for (int j = 0; j < BN; ++j) {
            float pv[4];
            #pragma unroll
            for (int i = 0; i < 4; ++i) pv[i] = Ps[(4 * ty + i) * PS_STR + j];  // broadcast
            float4 va = *reinterpret_cast<const float4*>(&KV[j * VS_STR + 8 * tx]);
            float4 vb = *reinterpret_cast<const float4*>(&KV[j * VS_STR + 8 * tx + 4]);
            #pragma unroll
            for (int i = 0; i < 4; ++i) {
                o[i][0] = fmaf(pv[i], va.x, o[i][0]);
                o[i][1] = fmaf(pv[i], va.y, o[i][1]);
                o[i][2] = fmaf(pv[i], va.z, o[i][2]);
                o[i][3] = fmaf(pv[i], va.w, o[i][3]);
                o[i][4] = fmaf(pv[i], vb.x, o[i][4]);
                o[i][5] = fmaf(pv[i], vb.y, o[i][5]);
                o[i][6] = fmaf(pv[i], vb.z, o[i][6]);
                o[i][7] = fmaf(pv[i], vb.w, o[i][7]);
            }
        }
    }

    // ---- epilogue: normalize and scatter (merge + inverse roll == same index map) ----
    #pragma unroll
    for (int i = 0; i < 4; ++i) {
        float inv = 1.f / lsum[i];
        int row = grow_idx(b, wy, wx, qbase + 4 * ty + i);
        float4 ra = make_float4(o[i][0] * inv, o[i][1] * inv, o[i][2] * inv, o[i][3] * inv);
        float4 rb = make_float4(o[i][4] * inv, o[i][5] * inv, o[i][6] * inv, o[i][7] * inv);
        float4* op = reinterpret_cast<float4*>(out + (size_t)row * C_DIM);
        op[2 * tx]     = ra;
        op[2 * tx + 1] = rb;
    }
}

extern "C" void kernel_launch(void* const* d_in, const int* in_sizes, int n_in,
                              void* d_out, int out_size) {
    (void)in_sizes; (void)n_in; (void)out_size;
    const float* q = (const float*)d_in[0];
    const float* k = (const float*)d_in[1];
    const float* v = (const float*)d_in[2];
    // d_in[3] (attn_mask) intentionally unused: mask recomputed inline from region ids.
    float* out = (float*)d_out;

    cudaFuncSetAttribute(swin_attn_kernel,
                         cudaFuncAttributeMaxDynamicSharedMemorySize, SMEM_BYTES);
    dim3 grid(NQT, 8 * 16);   // 12 query tiles x 128 windows
    swin_attn_kernel<<<grid, 256, SMEM_BYTES>>>(q, k, v, out);
}

// round 4
// speedup vs baseline: 3.4992x; 3.4992x over previous
#include <cuda_runtime.h>

// Shifted-window attention (UniMatch/Swin), B=8, H=96, W=128, C=128, NS=4.
// tf32 mma.sync flash-attention. Mask & roll recomputed inline (attn_mask input unused).

namespace {
constexpr int H_IMG = 96, W_IMG = 128, C_DIM = 128;
constexpr int WSH = 24, WSW = 32;       // window size
constexpr int SHF = 12, SWF = 16;       // shift
constexpr int BM = 64, BN = 64;
constexpr int NKT = 12, NQT = 12;       // 768 / 64
constexpr int QS_STR = 132;             // Q row-major  (stride ≡ 4 mod 32)
constexpr int KS_STR = 132;             // K row-major  (stride ≡ 4 mod 32)
constexpr int VS_STR = 136;             // V row-major  (stride ≡ 8 mod 32)
constexpr int PS_STR = 68;              // P row-major  (stride ≡ 4 mod 32)
constexpr int KV_FLOATS = BN * VS_STR;  // union buffer sized for the larger (V)
constexpr int SMEM_FLOATS = BM * QS_STR + KV_FLOATS + BM * PS_STR;
constexpr int SMEM_BYTES = SMEM_FLOATS * 4;   // 86016 B -> 2 CTAs/SM
constexpr float INV_SCALE = 0.088388347648318447f;  // 1/sqrt(128)
}

// token index within window -> global token row (roll(-12,-16) + split; self-inverse map)
__device__ __forceinline__ int grow_idx(int b, int wy, int wx, int t) {
    int r = t >> 5, cc = t & 31;
    int hi = wy * WSH + r + SHF; if (hi >= H_IMG) hi -= H_IMG;
    int wi = wx * WSW + cc + SWF; if (wi >= W_IMG) wi -= W_IMG;
    return b * (H_IMG * W_IMG) + hi * W_IMG + wi;
}

// Swin shift-mask region id
__device__ __forceinline__ int region_of(int wy, int wx, int t) {
    int r = t >> 5, cc = t & 31;
    int hh = wy * WSH + r;
    int ww = wx * WSW + cc;
    int rh = (hh < H_IMG - WSH) ? 0 : ((hh < H_IMG - SHF) ? 1 : 2);
    int rw = (ww < W_IMG - WSW) ? 0 : ((ww < W_IMG - SWF) ? 1 : 2);
    return rh * 3 + rw;
}

__device__ __forceinline__ float f2tf(float f) {
    unsigned r;
    asm("cvt.rna.tf32.f32 %0, %1;" : "=r"(r) : "f"(f));
    return __uint_as_float(r);
}

__device__ __forceinline__ void mma_tf32(float& c0, float& c1, float& c2, float& c3,
                                         unsigned a0, unsigned a1, unsigned a2, unsigned a3,
                                         unsigned b0, unsigned b1) {
    asm volatile(
        "mma.sync.aligned.m16n8k8.row.col.f32.tf32.tf32.f32 "
        "{%0,%1,%2,%3}, {%4,%5,%6,%7}, {%8,%9}, {%0,%1,%2,%3};"
        : "+f"(c0), "+f"(c1), "+f"(c2), "+f"(c3)
        : "r"(a0), "r"(a1), "r"(a2), "r"(a3), "r"(b0), "r"(b1));
}

__global__ __launch_bounds__(128, 2)
void swin_attn_mma(const float* __restrict__ q, const float* __restrict__ k,
                   const float* __restrict__ v, float* __restrict__ out) {
    extern __shared__ float smem[];
    float* Qs = smem;                 // [64][132] tf32
    float* KV = Qs + BM * QS_STR;     // K [64][132] / V [64][136] (time-shared)
    float* Ps = KV + KV_FLOATS;       // [64][68]

    const int tid  = threadIdx.x;
    const int lane = tid & 31;
    const int warp = tid >> 5;        // 0..3, owns rows 16*warp .. +15
    const int lr   = lane >> 2;       // 0..7
    const int lc   = lane & 3;        // 0..3

    const int win  = blockIdx.y;
    const int b    = win >> 4;
    const int widx = win & 15;
    const int wy   = widx >> 2;
    const int wx   = widx & 3;
    const int qbase = blockIdx.x * BM;

    // ---- load Q tile -> smem (tf32), coalesced float4 per lane per row ----
    #pragma unroll
    for (int s = 0; s < 16; ++s) {
        int local = warp * 16 + s;
        int row = grow_idx(b, wy, wx, qbase + local);
        float4 val = reinterpret_cast<const float4*>(q + (size_t)row * C_DIM)[lane];
        float4 tv = make_float4(f2tf(val.x), f2tf(val.y), f2tf(val.z), f2tf(val.w));
        *reinterpret_cast<float4*>(&Qs[local * QS_STR + lane * 4]) = tv;
    }

    const int tok_lo = qbase + warp * 16 + lr;   // this lane's two query rows
    const int tok_hi = tok_lo + 8;
    const int qreg_lo = region_of(wy, wx, tok_lo);
    const int qreg_hi = region_of(wy, wx, tok_hi);

    float o[16][4];                   // O fragments: 16 n-tiles of 8 channels
    #pragma unroll
    for (int t = 0; t < 16; ++t) { o[t][0] = o[t][1] = o[t][2] = o[t][3] = 0.f; }
    float m_lo = -1e30f, m_hi = -1e30f, l_lo = 0.f, l_hi = 0.f;

    for (int kt = 0; kt < NKT; ++kt) {
        const int kbase = kt * BN;
        __syncthreads();              // prior PV reads of KV/Ps complete

        // ---- load K tile (row-major, stride 132) ----
        #pragma unroll
        for (int s = 0; s < 16; ++s) {
            int local = warp * 16 + s;
            int row = grow_idx(b, wy, wx, kbase + local);
            float4 val = reinterpret_cast<const float4*>(k + (size_t)row * C_DIM)[lane];
            float4 tv = make_float4(f2tf(val.x), f2tf(val.y), f2tf(val.z), f2tf(val.w));
            *reinterpret_cast<float4*>(&KV[local * KS_STR + lane * 4]) = tv;
        }
        __syncthreads();

        // ---- S = Q K^T : warp computes 16x64 via 8 n-tiles x 16 k-steps ----
        float acc[8][4];
        #pragma unroll
        for (int t = 0; t < 8; ++t) { acc[t][0] = acc[t][1] = acc[t][2] = acc[t][3] = 0.f; }

        const float* Qrow = Qs + (warp * 16 + lr) * QS_STR + lc;
        #pragma unroll
        for (int k0 = 0; k0 < C_DIM; k0 += 8) {
            unsigned a0 = __float_as_uint(Qrow[k0]);
            unsigned a1 = __float_as_uint(Qrow[8 * QS_STR + k0]);
            unsigned a2 = __float_as_uint(Qrow[k0 + 4]);
            unsigned a3 = __float_as_uint(Qrow[8 * QS_STR + k0 + 4]);
            #pragma unroll
            for (int t = 0; t < 8; ++t) {
                const float* Bp = KV + (t * 8 + lr) * KS_STR + k0 + lc;
                unsigned b0 = __float_as_uint(Bp[0]);
                unsigned b1 = __float_as_uint(Bp[4]);
                mma_tf32(acc[t][0], acc[t][1], acc[t][2], acc[t][3], a0, a1, a2, a3, b0, b1);
            }
        }
        __syncthreads();              // all warps done reading K; KV may take V

        // ---- scale + mask + online softmax (warp-local; rows owned by warp) ----
        float tmax_lo = -1e30f, tmax_hi = -1e30f;
        #pragma unroll
        for (int t = 0; t < 8; ++t) {
            int c0 = kbase + 8 * t + 2 * lc;
            int r0 = region_of(wy, wx, c0);
            int r1 = region_of(wy, wx, c0 + 1);
            acc[t][0] = acc[t][0] * INV_SCALE + ((r0 == qreg_lo) ? 0.f : -100.f);
            acc[t][1] = acc[t][1] * INV_SCALE + ((r1 == qreg_lo) ? 0.f : -100.f);
            acc[t][2] = acc[t][2] * INV_SCALE + ((r0 == qreg_hi) ? 0.f : -100.f);
            acc[t][3] = acc[t][3] * INV_SCALE + ((r1 == qreg_hi) ? 0.f : -100.f);
            tmax_lo = fmaxf(tmax_lo, fmaxf(acc[t][0], acc[t][1]));
            tmax_hi = fmaxf(tmax_hi, fmaxf(acc[t][2], acc[t][3]));
        }
        tmax_lo = fmaxf(tmax_lo, __shfl_xor_sync(0xffffffffu, tmax_lo, 1));
        tmax_lo = fmaxf(tmax_lo, __shfl_xor_sync(0xffffffffu, tmax_lo, 2));
        tmax_hi = fmaxf(tmax_hi, __shfl_xor_sync(0xffffffffu, tmax_hi, 1));
        tmax_hi = fmaxf(tmax_hi, __shfl_xor_sync(0xffffffffu, tmax_hi, 2));

        float mnew_lo = fmaxf(m_lo, tmax_lo);
        float mnew_hi = fmaxf(m_hi, tmax_hi);
        float alpha_lo = __expf(m_lo - mnew_lo);
        float alpha_hi = __expf(m_hi - mnew_hi);
        m_lo = mnew_lo; m_hi = mnew_hi;

        float rs_lo = 0.f, rs_hi = 0.f;
        float* Prow = Ps + (warp * 16 + lr) * PS_STR + 2 * lc;
        #pragma unroll
        for (int t = 0; t < 8; ++t) {
            float p0 = f2tf(__expf(acc[t][0] - m_lo));
            float p1 = f2tf(__expf(acc[t][1] - m_lo));
            float p2 = f2tf(__expf(acc[t][2] - m_hi));
            float p3 = f2tf(__expf(acc[t][3] - m_hi));
            rs_lo += p0 + p1;
            rs_hi += p2 + p3;
            *reinterpret_cast<float2*>(&Prow[8 * t]) = make_float2(p0, p1);
            *reinterpret_cast<float2*>(&Prow[8 * PS_STR + 8 * t]) = make_float2(p2, p3);
        }
        rs_lo += __shfl_xor_sync(0xffffffffu, rs_lo, 1);
        rs_lo += __shfl_xor_sync(0xffffffffu, rs_lo, 2);
        rs_hi += __shfl_xor_sync(0xffffffffu, rs_hi, 1);
        rs_hi += __shfl_xor_sync(0xffffffffu, rs_hi, 2);
        l_lo = l_lo * alpha_lo + rs_lo;
        l_hi = l_hi * alpha_hi + rs_hi;

        #pragma unroll
        for (int t = 0; t < 16; ++t) {
            o[t][0] *= alpha_lo; o[t][1] *= alpha_lo;
            o[t][2] *= alpha_hi; o[t][3] *= alpha_hi;
        }

        // ---- load V tile (row-major, stride 136) ----
        #pragma unroll
        for (int s = 0; s < 16; ++s) {
            int local = warp * 16 + s;
            int row = grow_idx(b, wy, wx, kbase + local);
            float4 val = reinterpret_cast<const float4*>(v + (size_t)row * C_DIM)[lane];
            float4 tv = make_float4(f2tf(val.x), f2tf(val.y), f2tf(val.z), f2tf(val.w));
            *reinterpret_cast<float4*>(&KV[local * VS_STR + lane * 4]) = tv;
        }
        __syncthreads();

        // ---- O += P V : 16 n-tiles x 8 k-steps ----
        const float* Pr = Ps + (warp * 16 + lr) * PS_STR + lc;
        #pragma unroll
        for (int k0 = 0; k0 < BN; k0 += 8) {
            unsigned a0 = __float_as_uint(Pr[k0]);
            unsigned a1 = __float_as_uint(Pr[8 * PS_STR + k0]);
            unsigned a2 = __float_as_uint(Pr[k0 + 4]);
            unsigned a3 = __float_as_uint(Pr[8 * PS_STR + k0 + 4]);
            #pragma unroll
            for (int t = 0; t < 16; ++t) {
                const float* Bp = KV + (k0 + lc) * VS_STR + t * 8 + lr;
                unsigned b0 = __float_as_uint(Bp[0]);
                unsigned b1 = __float_as_uint(Bp[4 * VS_STR]);
                mma_tf32(o[t][0], o[t][1], o[t][2], o[t][3], a0, a1, a2, a3, b0, b1);
            }
        }
    }

    // ---- epilogue: normalize + scatter (merge + inverse roll == same map) ----
    const int gr_lo = grow_idx(b, wy, wx, tok_lo);
    const int gr_hi = grow_idx(b, wy, wx, tok_hi);
    const float ilo = 1.f / l_lo;
    const float ihi = 1.f / l_hi;
    float* out_lo = out + (size_t)gr_lo * C_DIM + 2 * lc;
    float* out_hi = out + (size_t)gr_hi * C_DIM + 2 * lc;
    #pragma unroll
    for (int t = 0; t < 16; ++t) {
        *reinterpret_cast<float2*>(&out_lo[8 * t]) = make_float2(o[t][0] * ilo, o[t][1] * ilo);
        *reinterpret_cast<float2*>(&out_hi[8 * t]) = make_float2(o[t][2] * ihi, o[t][3] * ihi);
    }
}

extern "C" void kernel_launch(void* const* d_in, const int* in_sizes, int n_in,
                              void* d_out, int out_size) {
    (void)in_sizes; (void)n_in; (void)out_size;
    const float* q = (const float*)d_in[0];
    const float* k = (const float*)d_in[1];
    const float* v = (const float*)d_in[2];
    float* out = (float*)d_out;

    cudaFuncSetAttribute(swin_attn_mma,
                         cudaFuncAttributeMaxDynamicSharedMemorySize, SMEM_BYTES);
    dim3 grid(NQT, 8 * 16);   // 12 Q-tiles x 128 windows (x-fastest keeps window in L2)
    swin_attn_mma<<<grid, 128, SMEM_BYTES>>>(q, k, v, out);
}

// round 5
// speedup vs baseline: 6.3131x; 1.8042x over previous
#include <cuda_runtime.h>
#include <cuda_fp16.h>

// Shifted-window attention (UniMatch/Swin), B=8, H=96, W=128, C=128, NS=4.
// fp16 mma.m16n8k16 flash-attention, ldmatrix fragments, P kept in registers.
// Mask & roll computed inline (attn_mask input unused).

namespace {
constexpr int H_IMG = 96, W_IMG = 128, C_DIM = 128;
constexpr int WSH = 24, WSW = 32;       // window size
constexpr int SHF = 12, SWF = 16;       // shift
constexpr int BM = 64, BN = 64;
constexpr int NKT = 12, NQT = 12;       // 768 / 64
constexpr int STR = 136;                // half-element row stride (272B ≡ 16 mod 128 -> LDSM conflict-free)
constexpr int TILE_HALFS = 64 * STR;    // one 64x128(+pad) fp16 tile
constexpr int SMEM_BYTES = 3 * TILE_HALFS * 2;   // Q + K + V = 52224 B
constexpr float INV_SCALE = 0.088388347648318447f;  // 1/sqrt(128)
}

// token index within window -> global token row (roll(-12,-16) + split; self-inverse map)
__device__ __forceinline__ int grow_idx(int b, int wy, int wx, int t) {
    int r = t >> 5, cc = t & 31;
    int hi = wy * WSH + r + SHF; if (hi >= H_IMG) hi -= H_IMG;
    int wi = wx * WSW + cc + SWF; if (wi >= W_IMG) wi -= W_IMG;
    return b * (H_IMG * W_IMG) + hi * W_IMG + wi;
}

// Swin shift-mask region id
__device__ __forceinline__ int region_of(int wy, int wx, int t) {
    int r = t >> 5, cc = t & 31;
    int hh = wy * WSH + r;
    int ww = wx * WSW + cc;
    int rh = (hh < H_IMG - WSH) ? 0 : ((hh < H_IMG - SHF) ? 1 : 2);
    int rw = (ww < W_IMG - WSW) ? 0 : ((ww < W_IMG - SWF) ? 1 : 2);
    return rh * 3 + rw;
}

__device__ __forceinline__ void mma_f16(float& c0, float& c1, float& c2, float& c3,
                                        unsigned a0, unsigned a1, unsigned a2, unsigned a3,
                                        unsigned b0, unsigned b1) {
    asm volatile(
        "mma.sync.aligned.m16n8k16.row.col.f32.f16.f16.f32 "
        "{%0,%1,%2,%3}, {%4,%5,%6,%7}, {%8,%9}, {%0,%1,%2,%3};"
        : "+f"(c0), "+f"(c1), "+f"(c2), "+f"(c3)
        : "r"(a0), "r"(a1), "r"(a2), "r"(a3), "r"(b0), "r"(b1));
}

#define LDSM_X4(r0, r1, r2, r3, addr)                                            \
    asm volatile("ldmatrix.sync.aligned.m8n8.x4.shared.b16 {%0,%1,%2,%3}, [%4];" \
                 : "=r"(r0), "=r"(r1), "=r"(r2), "=r"(r3) : "r"(addr))

#define LDSM_X4_T(r0, r1, r2, r3, addr)                                                \
    asm volatile("ldmatrix.sync.aligned.m8n8.x4.trans.shared.b16 {%0,%1,%2,%3}, [%4];" \
                 : "=r"(r0), "=r"(r1), "=r"(r2), "=r"(r3) : "r"(addr))

__device__ __forceinline__ unsigned h2u(__half2 h) { return *reinterpret_cast<unsigned*>(&h); }

// load one 64-token fp16 tile from gmem (f32) into smem, rolled/split addressing
__device__ __forceinline__ void load_tile_f16(const float* __restrict__ src, __half* dst,
                                              int b, int wy, int wx, int tbase,
                                              int warp, int lane) {
    #pragma unroll
    for (int s = 0; s < 16; ++s) {
        int local = warp * 16 + s;
        int row = grow_idx(b, wy, wx, tbase + local);
        float4 val = reinterpret_cast<const float4*>(src + (size_t)row * C_DIM)[lane];
        __half2 h01 = __floats2half2_rn(val.x, val.y);
        __half2 h23 = __floats2half2_rn(val.z, val.w);
        *reinterpret_cast<uint2*>(dst + local * STR + lane * 4) =
            make_uint2(h2u(h01), h2u(h23));
    }
}

__global__ __launch_bounds__(128, 3)
void swin_attn_f16(const float* __restrict__ q, const float* __restrict__ k,
                   const float* __restrict__ v, float* __restrict__ out) {
    extern __shared__ __half smem[];
    __half* Qs = smem;                  // [64][136]
    __half* Ks = Qs + TILE_HALFS;       // [64][136]
    __half* Vs = Ks + TILE_HALFS;       // [64][136]

    const int tid  = threadIdx.x;
    const int lane = tid & 31;
    const int warp = tid >> 5;          // owns q-rows 16*warp .. +15
    const int lr   = lane >> 2;         // 0..7
    const int lc   = lane & 3;          // 0..3

    const int win  = blockIdx.y;
    const int b    = win >> 4;
    const int widx = win & 15;
    const int wy   = widx >> 2;
    const int wx   = widx & 3;
    const int qbase = blockIdx.x * BM;

    // ---- Q tile -> smem fp16 (once) ----
    load_tile_f16(q, Qs, b, wy, wx, qbase, warp, lane);

    const int tok_lo = qbase + warp * 16 + lr;
    const int tok_hi = tok_lo + 8;
    const int qreg_lo = region_of(wy, wx, tok_lo);
    const int qreg_hi = region_of(wy, wx, tok_hi);

    // ldmatrix lane-address bases (byte addresses in shared space)
    const unsigned q_lds = (unsigned)__cvta_generic_to_shared(Qs) +
        (((warp * 16 + (lane & 15)) * STR + ((lane & 16) >> 1)) * 2);
    const unsigned k_lds = (unsigned)__cvta_generic_to_shared(Ks) +
        ((((lane & 7) + ((lane & 16) >> 1)) * STR + (lane & 8)) * 2);
    const unsigned v_lds = (unsigned)__cvta_generic_to_shared(Vs) +
        ((((lane & 7) + (lane & 8)) * STR + ((lane & 16) >> 1)) * 2);

    float o[16][4];
    #pragma unroll
    for (int t = 0; t < 16; ++t) { o[t][0] = o[t][1] = o[t][2] = o[t][3] = 0.f; }
    float m_lo = -1e30f, m_hi = -1e30f, l_lo = 0.f, l_hi = 0.f;

    for (int kt = 0; kt < NKT; ++kt) {
        const int kbase = kt * BN;

        // ---- load K and V tiles (batched LDGs for MLP) ----
        load_tile_f16(k, Ks, b, wy, wx, kbase, warp, lane);
        load_tile_f16(v, Vs, b, wy, wx, kbase, warp, lane);
        __syncthreads();

        // ---- S = Q K^T : 8 k-steps (k=16) x 8 n-tiles ----
        float acc[8][4];
        #pragma unroll
        for (int t = 0; t < 8; ++t) { acc[t][0] = acc[t][1] = acc[t][2] = acc[t][3] = 0.f; }

        #pragma unroll
        for (int kk = 0; kk < 8; ++kk) {
            unsigned a0, a1, a2, a3;
            LDSM_X4(a0, a1, a2, a3, q_lds + kk * 32);
            #pragma unroll
            for (int tp = 0; tp < 4; ++tp) {
                unsigned b0, b1, b2, b3;
                LDSM_X4(b0, b1, b2, b3, k_lds + tp * (16 * STR * 2) + kk * 32);
                mma_f16(acc[2*tp][0], acc[2*tp][1], acc[2*tp][2], acc[2*tp][3],
                        a0, a1, a2, a3, b0, b1);
                mma_f16(acc[2*tp+1][0], acc[2*tp+1][1], acc[2*tp+1][2], acc[2*tp+1][3],
                        a0, a1, a2, a3, b2, b3);
            }
        }

        // ---- scale + mask + online softmax (warp-local) ----
        float tmax_lo = -1e30f, tmax_hi = -1e30f;
        #pragma unroll
        for (int t = 0; t < 8; ++t) {
            int c0 = kbase + 8 * t + 2 * lc;
            int r0 = region_of(wy, wx, c0);
            int r1 = region_of(wy, wx, c0 + 1);
            acc[t][0] = acc[t][0] * INV_SCALE + ((r0 == qreg_lo) ? 0.f : -100.f);
            acc[t][1] = acc[t][1] * INV_SCALE + ((r1 == qreg_lo) ? 0.f : -100.f);
            acc[t][2] = acc[t][2] * INV_SCALE + ((r0 == qreg_hi) ? 0.f : -100.f);
            acc[t][3] = acc[t][3] * INV_SCALE + ((r1 == qreg_hi) ? 0.f : -100.f);
            tmax_lo = fmaxf(tmax_lo, fmaxf(acc[t][0], acc[t][1]));
            tmax_hi = fmaxf(tmax_hi, fmaxf(acc[t][2], acc[t][3]));
        }
        tmax_lo = fmaxf(tmax_lo, __shfl_xor_sync(0xffffffffu, tmax_lo, 1));
        tmax_lo = fmaxf(tmax_lo, __shfl_xor_sync(0xffffffffu, tmax_lo, 2));
        tmax_hi = fmaxf(tmax_hi, __shfl_xor_sync(0xffffffffu, tmax_hi, 1));
        tmax_hi = fmaxf(tmax_hi, __shfl_xor_sync(0xffffffffu, tmax_hi, 2));

        float mnew_lo = fmaxf(m_lo, tmax_lo);
        float mnew_hi = fmaxf(m_hi, tmax_hi);
        float alpha_lo = __expf(m_lo - mnew_lo);
        float alpha_hi = __expf(m_hi - mnew_hi);
        m_lo = mnew_lo; m_hi = mnew_hi;

        float rs_lo = 0.f, rs_hi = 0.f;
        #pragma unroll
        for (int t = 0; t < 8; ++t) {
            acc[t][0] = __expf(acc[t][0] - m_lo);
            acc[t][1] = __expf(acc[t][1] - m_lo);
            acc[t][2] = __expf(acc[t][2] - m_hi);
            acc[t][3] = __expf(acc[t][3] - m_hi);
            rs_lo += acc[t][0] + acc[t][1];
            rs_hi += acc[t][2] + acc[t][3];
        }
        rs_lo += __shfl_xor_sync(0xffffffffu, rs_lo, 1);
        rs_lo += __shfl_xor_sync(0xffffffffu, rs_lo, 2);
        rs_hi += __shfl_xor_sync(0xffffffffu, rs_hi, 1);
        rs_hi += __shfl_xor_sync(0xffffffffu, rs_hi, 2);
        l_lo = l_lo * alpha_lo + rs_lo;
        l_hi = l_hi * alpha_hi + rs_hi;

        // ---- P (registers only): S-accum fragments -> A fragments ----
        unsigned pa[4][4];
        #pragma unroll
        for (int s = 0; s < 4; ++s) {
            pa[s][0] = h2u(__floats2half2_rn(acc[2*s][0],   acc[2*s][1]));
            pa[s][1] = h2u(__floats2half2_rn(acc[2*s][2],   acc[2*s][3]));
            pa[s][2] = h2u(__floats2half2_rn(acc[2*s+1][0], acc[2*s+1][1]));
            pa[s][3] = h2u(__floats2half2_rn(acc[2*s+1][2], acc[2*s+1][3]));
        }

        // ---- rescale O ----
        #pragma unroll
        for (int t = 0; t < 16; ++t) {
            o[t][0] *= alpha_lo; o[t][1] *= alpha_lo;
            o[t][2] *= alpha_hi; o[t][3] *= alpha_hi;
        }

        // ---- O += P V : 4 k-steps (16 tokens) x 8 ch-tile-pairs ----
        #pragma unroll
        for (int s = 0; s < 4; ++s) {
            #pragma unroll
            for (int cp = 0; cp < 8; ++cp) {
                unsigned b0, b1, b2, b3;
                LDSM_X4_T(b0, b1, b2, b3, v_lds + s * (16 * STR * 2) + cp * 32);
                mma_f16(o[2*cp][0], o[2*cp][1], o[2*cp][2], o[2*cp][3],
                        pa[s][0], pa[s][1], pa[s][2], pa[s][3], b0, b1);
                mma_f16(o[2*cp+1][0], o[2*cp+1][1], o[2*cp+1][2], o[2*cp+1][3],
                        pa[s][0], pa[s][1], pa[s][2], pa[s][3], b2, b3);
            }
        }
        __syncthreads();   // all warps done reading Ks/Vs before next iter overwrites
    }

    // ---- epilogue: normalize + scatter (merge + inverse roll == same map) ----
    const int gr_lo = grow_idx(b, wy, wx, tok_lo);
    const int gr_hi = grow_idx(b, wy, wx, tok_hi);
    const float ilo = 1.f / l_lo;
    const float ihi = 1.f / l_hi;
    float* out_lo = out + (size_t)gr_lo * C_DIM + 2 * lc;
    float* out_hi = out + (size_t)gr_hi * C_DIM + 2 * lc;
    #pragma unroll
    for (int t = 0; t < 16; ++t) {
        *reinterpret_cast<float2*>(&out_lo[8 * t]) = make_float2(o[t][0] * ilo, o[t][1] * ilo);
        *reinterpret_cast<float2*>(&out_hi[8 * t]) = make_float2(o[t][2] * ihi, o[t][3] * ihi);
    }
}

extern "C" void kernel_launch(void* const* d_in, const int* in_sizes, int n_in,
                              void* d_out, int out_size) {
    (void)in_sizes; (void)n_in; (void)out_size;
    const float* q = (const float*)d_in[0];
    const float* k = (const float*)d_in[1];
    const float* v = (const float*)d_in[2];
    float* out = (float*)d_out;

    cudaFuncSetAttribute(swin_attn_f16,
                         cudaFuncAttributeMaxDynamicSharedMemorySize, SMEM_BYTES);
    dim3 grid(NQT, 8 * 16);   // 12 Q-tiles x 128 windows
    swin_attn_f16<<<grid, 128, SMEM_BYTES>>>(q, k, v, out);
}